// round 14
// baseline (speedup 1.0000x reference)
#include <cuda_runtime.h>
#include <math.h>
#include <stdint.h>

#define T_   512
#define B_   256
#define OBS_ 128
#define ACT_ 32
#define HID_ 512
#define HF_  512
#define IN_  160
#define G3_  1536

__device__ float g_X  [(size_t)T_ * B_ * IN_];
__device__ float g_gi [(size_t)T_ * B_ * G3_];
__device__ float g_gi0[(size_t)B_ * G3_];
__device__ float g_hs [(size_t)T_ * B_ * HID_];
__device__ float g_t1 [(size_t)T_ * B_ * G3_];
__device__ float g_t2 [(size_t)T_ * B_ * HF_];
__device__ float g_whi[(size_t)G3_ * HID_];
__device__ float g_wlo[(size_t)G3_ * HID_];
__device__ float g_wcat[(size_t)3 * HF_ * HID_];
__device__ float g_bcat[3 * HF_];
__device__ unsigned g_bar;
__device__ double g_acc;

__device__ __forceinline__ void split2(float x, uint32_t& hi, uint32_t& lo)
{
    uint32_t hb = __float_as_uint(x) & 0xFFFFE000u;
    hi = hb;
    lo = __float_as_uint(x - __uint_as_float(hb));
}

__device__ __forceinline__ void mma_tf32(float* c,
                                         uint32_t a0, uint32_t a1, uint32_t a2, uint32_t a3,
                                         uint32_t b0, uint32_t b1)
{
    asm volatile(
        "mma.sync.aligned.m16n8k8.row.col.f32.tf32.tf32.f32 "
        "{%0,%1,%2,%3}, {%4,%5,%6,%7}, {%8,%9}, {%0,%1,%2,%3};"
        : "+f"(c[0]), "+f"(c[1]), "+f"(c[2]), "+f"(c[3])
        : "r"(a0), "r"(a1), "r"(a2), "r"(a3), "r"(b0), "r"(b1));
}

// ---------- tensor-core GEMM: CTA 128x128, warp 64x32, BK=16 ----------
template <int ACTMODE, int ALIGNED>
__global__ void __launch_bounds__(256) gemm_tc(
    const float* __restrict__ A, int lda,
    const float* __restrict__ B, int ldb,
    const float* __restrict__ bias,
    float* __restrict__ C, int ldc,
    int M, int N, int K)
{
    __shared__ float As[2][16][136];
    __shared__ float Bs[2][16][136];

    const int bm = blockIdx.y * 128;
    const int bn = blockIdx.x * 128;
    const int tid  = threadIdx.x;
    const int warp = tid >> 5, lane = tid & 31;
    const int wm = (warp >> 2) * 64;
    const int wn = (warp & 3) * 32;
    const int g  = lane >> 2;
    const int tg = lane & 3;
    const int r0 = tid >> 2;
    const int q0 = (tid & 3) << 2;

    float acc[4][4][4];
#pragma unroll
    for (int mi = 0; mi < 4; mi++)
#pragma unroll
        for (int ni = 0; ni < 4; ni++)
#pragma unroll
            for (int r = 0; r < 4; r++) acc[mi][ni][r] = 0.f;

    const int niter = K >> 4;
    const float4 z4 = make_float4(0.f, 0.f, 0.f, 0.f);

    float4 sa0, sa1, sb0, sb1;
    sa0 = *(const float4*)(A + (size_t)(bm + r0) * lda + q0);
    sa1 = *(const float4*)(A + (size_t)(bm + r0 + 64) * lda + q0);
    sb0 = (bn + r0      < N) ? *(const float4*)(B + (size_t)(bn + r0) * ldb + q0)      : z4;
    sb1 = (bn + r0 + 64 < N) ? *(const float4*)(B + (size_t)(bn + r0 + 64) * ldb + q0) : z4;

    As[0][q0 + 0][r0] = sa0.x; As[0][q0 + 1][r0] = sa0.y;
    As[0][q0 + 2][r0] = sa0.z; As[0][q0 + 3][r0] = sa0.w;
    As[0][q0 + 0][r0 + 64] = sa1.x; As[0][q0 + 1][r0 + 64] = sa1.y;
    As[0][q0 + 2][r0 + 64] = sa1.z; As[0][q0 + 3][r0 + 64] = sa1.w;
    Bs[0][q0 + 0][r0] = sb0.x; Bs[0][q0 + 1][r0] = sb0.y;
    Bs[0][q0 + 2][r0] = sb0.z; Bs[0][q0 + 3][r0] = sb0.w;
    Bs[0][q0 + 0][r0 + 64] = sb1.x; Bs[0][q0 + 1][r0 + 64] = sb1.y;
    Bs[0][q0 + 2][r0 + 64] = sb1.z; Bs[0][q0 + 3][r0 + 64] = sb1.w;
    __syncthreads();

    for (int it = 0; it < niter; ++it) {
        const int buf = it & 1;
        const bool have_next = (it + 1 < niter);
        if (have_next) {
            const int k0 = (it + 1) << 4;
            sa0 = *(const float4*)(A + (size_t)(bm + r0) * lda + k0 + q0);
            sa1 = *(const float4*)(A + (size_t)(bm + r0 + 64) * lda + k0 + q0);
            sb0 = (bn + r0      < N) ? *(const float4*)(B + (size_t)(bn + r0) * ldb + k0 + q0)      : z4;
            sb1 = (bn + r0 + 64 < N) ? *(const float4*)(B + (size_t)(bn + r0 + 64) * ldb + k0 + q0) : z4;
        }

#pragma unroll
        for (int kk = 0; kk < 16; kk += 8) {
            uint32_t ah[4][4], al[4][4];
#pragma unroll
            for (int mi = 0; mi < 4; mi++) {
                const int m = wm + mi * 16 + g;
                split2(As[buf][kk + tg][m],         ah[mi][0], al[mi][0]);
                split2(As[buf][kk + tg][m + 8],     ah[mi][1], al[mi][1]);
                split2(As[buf][kk + tg + 4][m],     ah[mi][2], al[mi][2]);
                split2(As[buf][kk + tg + 4][m + 8], ah[mi][3], al[mi][3]);
            }
            uint32_t bh[4][2], bl[4][2];
#pragma unroll
            for (int ni = 0; ni < 4; ni++) {
                const int n = wn + ni * 8 + g;
                split2(Bs[buf][kk + tg][n],     bh[ni][0], bl[ni][0]);
                split2(Bs[buf][kk + tg + 4][n], bh[ni][1], bl[ni][1]);
            }
#pragma unroll
            for (int mi = 0; mi < 4; mi++)
#pragma unroll
                for (int ni = 0; ni < 4; ni++) {
                    float* c = acc[mi][ni];
                    mma_tf32(c, al[mi][0], al[mi][1], al[mi][2], al[mi][3],
                             bh[ni][0], bh[ni][1]);
                    mma_tf32(c, ah[mi][0], ah[mi][1], ah[mi][2], ah[mi][3],
                             bl[ni][0], bl[ni][1]);
                    mma_tf32(c, ah[mi][0], ah[mi][1], ah[mi][2], ah[mi][3],
                             bh[ni][0], bh[ni][1]);
                }
        }

        if (have_next) {
            const int nb = buf ^ 1;
            As[nb][q0 + 0][r0] = sa0.x; As[nb][q0 + 1][r0] = sa0.y;
            As[nb][q0 + 2][r0] = sa0.z; As[nb][q0 + 3][r0] = sa0.w;
            As[nb][q0 + 0][r0 + 64] = sa1.x; As[nb][q0 + 1][r0 + 64] = sa1.y;
            As[nb][q0 + 2][r0 + 64] = sa1.z; As[nb][q0 + 3][r0 + 64] = sa1.w;
            Bs[nb][q0 + 0][r0] = sb0.x; Bs[nb][q0 + 1][r0] = sb0.y;
            Bs[nb][q0 + 2][r0] = sb0.z; Bs[nb][q0 + 3][r0] = sb0.w;
            Bs[nb][q0 + 0][r0 + 64] = sb1.x; Bs[nb][q0 + 1][r0 + 64] = sb1.y;
            Bs[nb][q0 + 2][r0 + 64] = sb1.z; Bs[nb][q0 + 3][r0 + 64] = sb1.w;
            __syncthreads();
        }
    }

#pragma unroll
    for (int mi = 0; mi < 4; mi++) {
        const int row = bm + wm + mi * 16 + g;
#pragma unroll
        for (int ni = 0; ni < 4; ni++) {
            const int col = bn + wn + ni * 8 + tg * 2;
            if (col < N) {
                const float* c = acc[mi][ni];
                float v0 = c[0] + bias[col];
                float v1 = c[1] + bias[col + 1];
                float v2 = c[2] + bias[col];
                float v3 = c[3] + bias[col + 1];
                if (ACTMODE == 1) {
                    v0 = v0 > 0.f ? v0 : expm1f(v0);
                    v1 = v1 > 0.f ? v1 : expm1f(v1);
                    v2 = v2 > 0.f ? v2 : expm1f(v2);
                    v3 = v3 > 0.f ? v3 : expm1f(v3);
                }
                if (ALIGNED) {
                    *(float2*)(C + (size_t)row * ldc + col)       = make_float2(v0, v1);
                    *(float2*)(C + (size_t)(row + 8) * ldc + col) = make_float2(v2, v3);
                } else {
                    C[(size_t)row * ldc + col]           = v0;
                    C[(size_t)row * ldc + col + 1]       = v1;
                    C[(size_t)(row + 8) * ldc + col]     = v2;
                    C[(size_t)(row + 8) * ldc + col + 1] = v3;
                }
            }
        }
    }
}

// ---------------- weight presplit + concat ----------------
__global__ void split_w(const float* __restrict__ w, float* __restrict__ hi,
                        float* __restrict__ lo, int n)
{
    int i = blockIdx.x * blockDim.x + threadIdx.x;
    if (i >= n) return;
    float x = w[i];
    uint32_t hb = __float_as_uint(x) & 0xFFFFE000u;
    float h = __uint_as_float(hb);
    hi[i] = h;
    lo[i] = x - h;
}

__global__ void concat_w(const float* __restrict__ w0, const float* __restrict__ w1,
                         const float* __restrict__ w2,
                         const float* __restrict__ b0, const float* __restrict__ b1,
                         const float* __restrict__ b2)
{
    int i = blockIdx.x * blockDim.x + threadIdx.x;
    const int n = HF_ * HID_;
    if (i < n) {
        g_wcat[i]         = w0[i];
        g_wcat[n + i]     = w1[i];
        g_wcat[2 * n + i] = w2[i];
    }
    if (i < HF_) {
        g_bcat[i]           = b0[i];
        g_bcat[HF_ + i]     = b1[i];
        g_bcat[2 * HF_ + i] = b2[i];
    }
}

// ============ persistent tensor-core GRU, split accumulators ============
#define GRU_SMEM 92160
#define HS_STR 68
#define W_STR  56
#define GH_STR 52
#define NCTAS 128u
__global__ void __launch_bounds__(256) gru_persist(
    const float* __restrict__ whi, const float* __restrict__ wlo,
    const float* __restrict__ b_hh)
{
    extern __shared__ float sm[];
    const int n0 = blockIdx.x * 16;
    const int m0 = blockIdx.y * 64;
    const int tid  = threadIdx.x;
    const int warp = tid >> 5, lane = tid & 31;
    const int wm = (warp & 3) * 16;
    const int wn = (warp >> 2) * 24;
    const int g  = lane >> 2;
    const int tg = lane & 3;
    const int hr = tid >> 2;
    const int hc4 = (tid & 3) << 2;

    float4 sh[4], sw[6];

#define GRU_LDG(H, K0)                                                         \
    do {                                                                       \
        _Pragma("unroll")                                                      \
        for (int s = 0; s < 4; s++)                                            \
            sh[s] = *(const float4*)((H) + (size_t)(m0 + hr) * HID_ + (K0) + s * 16 + hc4); \
        _Pragma("unroll")                                                      \
        for (int s = 0; s < 6; s++) {                                          \
            int f = tid + (s << 8);                                            \
            int i = f >> 4;                                                    \
            int c4 = (f & 15) << 2;                                            \
            int i48 = (i < 48) ? i : i - 48;                                   \
            const float* src = (i < 48) ? whi : wlo;                           \
            int grow = (i48 >> 4) * HID_ + n0 + (i48 & 15);                    \
            sw[s] = *(const float4*)(src + (size_t)grow * HID_ + (K0) + c4);   \
        }                                                                      \
    } while (0)

#define GRU_STS(BUF)                                                           \
    do {                                                                       \
        float* hp = sm + (BUF) * 11520;                                        \
        _Pragma("unroll")                                                      \
        for (int s = 0; s < 4; s++) {                                          \
            int kb = s * 16 + hc4;                                             \
            hp[(kb + 0) * HS_STR + hr] = sh[s].x;                              \
            hp[(kb + 1) * HS_STR + hr] = sh[s].y;                              \
            hp[(kb + 2) * HS_STR + hr] = sh[s].z;                              \
            hp[(kb + 3) * HS_STR + hr] = sh[s].w;                              \
        }                                                                      \
        _Pragma("unroll")                                                      \
        for (int s = 0; s < 6; s++) {                                          \
            int f = tid + (s << 8);                                            \
            int i = f >> 4;                                                    \
            int c4 = (f & 15) << 2;                                            \
            int i48 = (i < 48) ? i : i - 48;                                   \
            float* wp = sm + (BUF) * 11520 + 4352 + ((i < 48) ? 0 : 3584);     \
            wp[(c4 + 0) * W_STR + i48] = sw[s].x;                              \
            wp[(c4 + 1) * W_STR + i48] = sw[s].y;                              \
            wp[(c4 + 2) * W_STR + i48] = sw[s].z;                              \
            wp[(c4 + 3) * W_STR + i48] = sw[s].w;                              \
        }                                                                      \
    } while (0)

    for (int t = 0; t < T_ - 1; ++t) {
        const float* h  = g_hs + (size_t)t * B_ * HID_;
        const float* gi = g_gi + (size_t)t * B_ * G3_;
        float* h_next   = g_hs + (size_t)(t + 1) * B_ * HID_;

        // three independent accumulator sets -> 9 independent HMMA chains/warp
        float accA[3][4], accB[3][4], accC[3][4];
#pragma unroll
        for (int ni = 0; ni < 3; ni++)
#pragma unroll
            for (int r = 0; r < 4; r++) {
                accA[ni][r] = 0.f; accB[ni][r] = 0.f; accC[ni][r] = 0.f;
            }

        GRU_LDG(h, 0);
        GRU_STS(0);
        __syncthreads();

        const int NIT = HID_ / 64;   // 8
        for (int it = 0; it < NIT; ++it) {
            const int buf = it & 1;
            const float* Hb = sm + buf * 11520;
            const float* Wh = Hb + 4352;
            const float* Wl = Wh + 3584;
            const bool have_next = (it + 1 < NIT);
            if (have_next) GRU_LDG(h, (it + 1) * 64);

#pragma unroll
            for (int kk = 0; kk < 64; kk += 8) {
                uint32_t ah[4], al[4];
                split2(Hb[(kk + tg) * HS_STR + wm + g],         ah[0], al[0]);
                split2(Hb[(kk + tg) * HS_STR + wm + g + 8],     ah[1], al[1]);
                split2(Hb[(kk + tg + 4) * HS_STR + wm + g],     ah[2], al[2]);
                split2(Hb[(kk + tg + 4) * HS_STR + wm + g + 8], ah[3], al[3]);
#pragma unroll
                for (int ni = 0; ni < 3; ni++) {
                    const int n = wn + ni * 8 + g;
                    uint32_t bh0 = __float_as_uint(Wh[(kk + tg) * W_STR + n]);
                    uint32_t bh1 = __float_as_uint(Wh[(kk + tg + 4) * W_STR + n]);
                    uint32_t bl0 = __float_as_uint(Wl[(kk + tg) * W_STR + n]);
                    uint32_t bl1 = __float_as_uint(Wl[(kk + tg + 4) * W_STR + n]);
                    mma_tf32(accA[ni], al[0], al[1], al[2], al[3], bh0, bh1);
                    mma_tf32(accB[ni], ah[0], ah[1], ah[2], ah[3], bl0, bl1);
                    mma_tf32(accC[ni], ah[0], ah[1], ah[2], ah[3], bh0, bh1);
                }
            }

            if (have_next) {
                GRU_STS(buf ^ 1);
                __syncthreads();
            }
        }

        // stage gh into buf0 Hs region (disjoint from buf1 used by last iter)
        float* gh = sm;
#pragma unroll
        for (int ni = 0; ni < 3; ni++) {
            const int col = wn + ni * 8 + tg * 2;
            float c0 = accA[ni][0] + accB[ni][0] + accC[ni][0];
            float c1 = accA[ni][1] + accB[ni][1] + accC[ni][1];
            float c2 = accA[ni][2] + accB[ni][2] + accC[ni][2];
            float c3 = accA[ni][3] + accB[ni][3] + accC[ni][3];
            gh[(wm + g) * GH_STR + col]         = c0;
            gh[(wm + g) * GH_STR + col + 1]     = c1;
            gh[(wm + g + 8) * GH_STR + col]     = c2;
            gh[(wm + g + 8) * GH_STR + col + 1] = c3;
        }
        __syncthreads();

        {
            const int ml = tid >> 2;
            const int nb = (tid & 3) << 2;
            const float* gir = gi + (size_t)(m0 + ml) * G3_;
            const float* hrow = h + (size_t)(m0 + ml) * HID_;
            float* orow = h_next + (size_t)(m0 + ml) * HID_;
#pragma unroll
            for (int j = 0; j < 4; j++) {
                const int nl = nb + j;
                const int n = n0 + nl;
                float ghr = gh[ml * GH_STR + nl]      + b_hh[n];
                float ghz = gh[ml * GH_STR + 16 + nl] + b_hh[512 + n];
                float ghn = gh[ml * GH_STR + 32 + nl] + b_hh[1024 + n];
                float r  = 1.f / (1.f + expf(-(gir[n] + ghr)));
                float z  = 1.f / (1.f + expf(-(gir[512 + n] + ghz)));
                float nn = tanhf(gir[1024 + n] + r * ghn);
                orow[n] = (1.f - z) * nn + z * hrow[n];
            }
        }

        if (t < T_ - 2) {
            __threadfence();
            __syncthreads();
            if (tid == 0) {
                atomicAdd(&g_bar, 1u);
                const unsigned target = NCTAS * (unsigned)(t + 1);
                while (*(volatile unsigned*)&g_bar < target) { }
            }
            __syncthreads();
            __threadfence();
        }
    }
}

// ---------------- pack X ----------------
__global__ void pack_x(const float* __restrict__ obs, const float* __restrict__ act)
{
    size_t i = (size_t)blockIdx.x * blockDim.x + threadIdx.x;
    const size_t n = (size_t)T_ * B_ * IN_;
    if (i >= n) return;
    size_t row = i / IN_;
    int c = (int)(i % IN_);
    g_X[i] = (c < OBS_) ? obs[row * OBS_ + c] : act[row * ACT_ + (c - OBS_)];
}

__global__ void h0_kernel(const float* __restrict__ b_hh)
{
    int i = blockIdx.x * blockDim.x + threadIdx.x;
    if (i == 0) g_bar = 0u;
    if (i >= B_ * HID_) return;
    int m = i >> 9, j = i & 511;
    const float* gr = g_gi0 + (size_t)m * G3_;
    float r  = 1.f / (1.f + expf(-(gr[j]        + b_hh[j])));
    float z  = 1.f / (1.f + expf(-(gr[512 + j]  + b_hh[512 + j])));
    float nn = tanhf(gr[1024 + j] + r * b_hh[1024 + j]);
    g_hs[i] = (1.f - z) * nn;
}

__global__ void gemv_rw(const float* __restrict__ A, const float* __restrict__ w,
                        const float* __restrict__ b, float* __restrict__ out, int M)
{
    int gw = (int)(((size_t)blockIdx.x * blockDim.x + threadIdx.x) >> 5);
    int lane = threadIdx.x & 31;
    if (gw >= M) return;
    const float* row = A + (size_t)gw * HF_;
    float s = 0.f;
#pragma unroll
    for (int k = lane; k < HF_; k += 32) s = fmaf(row[k], w[k], s);
#pragma unroll
    for (int o = 16; o; o >>= 1) s += __shfl_xor_sync(0xffffffffu, s, o);
    if (lane == 0) out[gw] = s + b[0];
}

__global__ void loss_init() { g_acc = 0.0; }

__global__ void sq_loss(const float* __restrict__ x, const float* __restrict__ mu,
                        size_t n, int shift)
{
    float s = 0.f;
    for (size_t i = (size_t)blockIdx.x * blockDim.x + threadIdx.x; i < n;
         i += (size_t)gridDim.x * blockDim.x) {
        float d = x[i] - mu[i >> shift];
        s = fmaf(0.5f * d, d, s);
    }
#pragma unroll
    for (int o = 16; o; o >>= 1) s += __shfl_xor_sync(0xffffffffu, s, o);
    __shared__ float ws[8];
    int lane = threadIdx.x & 31, w = threadIdx.x >> 5;
    if (lane == 0) ws[w] = s;
    __syncthreads();
    if (w == 0) {
        s = lane < (blockDim.x >> 5) ? ws[lane] : 0.f;
#pragma unroll
        for (int o = 4; o; o >>= 1) s += __shfl_xor_sync(0xffu, s, o);
        if (lane == 0) atomicAdd(&g_acc, (double)s);
    }
}

__global__ void finalize_loss(float* out)
{
    const double LOG2PI = 1.8378770664093453;
    out[0] = (float)(g_acc / (double)((size_t)T_ * B_) +
                     0.5 * LOG2PI * (double)(OBS_ + ACT_ + ACT_));
}

// ---------------- launch ----------------
extern "C" void kernel_launch(void* const* d_in, const int* in_sizes, int n_in,
                              void* d_out, int out_size)
{
    const float* obs    = (const float*)d_in[0];
    const float* action = (const float*)d_in[1];
    const float* w_ih = (const float*)d_in[3];
    const float* w_hh = (const float*)d_in[4];
    const float* b_ih = (const float*)d_in[5];
    const float* b_hh = (const float*)d_in[6];
    const float *ow0 = (const float*)d_in[7],  *ob0 = (const float*)d_in[8];
    const float *ow1 = (const float*)d_in[9],  *ob1 = (const float*)d_in[10];
    const float *ow2 = (const float*)d_in[11], *ob2 = (const float*)d_in[12];
    const float *aw0 = (const float*)d_in[13], *ab0 = (const float*)d_in[14];
    const float *aw1 = (const float*)d_in[15], *ab1 = (const float*)d_in[16];
    const float *aw2 = (const float*)d_in[17], *ab2 = (const float*)d_in[18];
    const float *rw0 = (const float*)d_in[19], *rb0 = (const float*)d_in[20];
    const float *rw1 = (const float*)d_in[21], *rb1 = (const float*)d_in[22];
    const float *rw2 = (const float*)d_in[23], *rb2 = (const float*)d_in[24];

    float* out = (float*)d_out;
    float* pre_obs = out + 1;
    float* pre_act = pre_obs + (size_t)T_ * B_ * OBS_;
    float* pre_rew = pre_act + (size_t)T_ * B_ * ACT_;

    float *pX, *pgi, *pgi0, *phs, *pt1, *pt2, *pwhi, *pwlo, *pwcat, *pbcat;
    cudaGetSymbolAddress((void**)&pX,   g_X);
    cudaGetSymbolAddress((void**)&pgi,  g_gi);
    cudaGetSymbolAddress((void**)&pgi0, g_gi0);
    cudaGetSymbolAddress((void**)&phs,  g_hs);
    cudaGetSymbolAddress((void**)&pt1,  g_t1);
    cudaGetSymbolAddress((void**)&pt2,  g_t2);
    cudaGetSymbolAddress((void**)&pwhi, g_whi);
    cudaGetSymbolAddress((void**)&pwlo, g_wlo);
    cudaGetSymbolAddress((void**)&pwcat, g_wcat);
    cudaGetSymbolAddress((void**)&pbcat, g_bcat);

    static int smem_set = 0;
    if (!smem_set) {
        cudaFuncSetAttribute(gru_persist, cudaFuncAttributeMaxDynamicSharedMemorySize, GRU_SMEM);
        smem_set = 1;
    }

    const int M = T_ * B_;  // 131072

    loss_init<<<1, 1>>>();

    {
        size_t n = (size_t)T_ * B_ * IN_;
        pack_x<<<(unsigned)((n + 255) / 256), 256>>>(obs, action);
    }

    split_w<<<(G3_ * HID_ + 255) / 256, 256>>>(w_hh, pwhi, pwlo, G3_ * HID_);
    concat_w<<<(HF_ * HID_ + 255) / 256, 256>>>(ow0, aw0, rw0, ob0, ab0, rb0);

    gemm_tc<0, 1><<<dim3(G3_ / 128, M / 128), 256>>>(
        pX, IN_, w_ih, IN_, b_ih, pgi, G3_, M, G3_, IN_);

    gemm_tc<0, 1><<<dim3(G3_ / 128, B_ / 128), 256>>>(
        obs, OBS_, w_ih, IN_, b_ih, pgi0, G3_, B_, G3_, OBS_);

    h0_kernel<<<(B_ * HID_ + 255) / 256, 256>>>(b_hh);

    gru_persist<<<dim3(HID_ / 16, B_ / 64), 256, GRU_SMEM>>>(pwhi, pwlo, b_hh);

    // ---- fused MLP layer 1 (obs|act|rew): [M,512] -> [M,1536] ----
    gemm_tc<1, 1><<<dim3(G3_ / 128, M / 128), 256>>>(
        phs, HID_, pwcat, HID_, pbcat, pt1, G3_, M, G3_, HID_);

    // ---- obs path ----
    gemm_tc<1, 1><<<dim3(HF_ / 128, M / 128), 256>>>(pt1, G3_, ow1, HF_, ob1, pt2, HF_, M, HF_, HF_);
    gemm_tc<0, 0><<<dim3(1, M / 128), 256>>>(pt2, HF_, ow2, HF_, ob2, pre_obs, OBS_, M, OBS_, HF_);
    sq_loss<<<4096, 256>>>(obs, pre_obs, (size_t)M * OBS_, 0);

    // ---- action path ----
    gemm_tc<1, 1><<<dim3(HF_ / 128, M / 128), 256>>>(pt1 + 512, G3_, aw1, HF_, ab1, pt2, HF_, M, HF_, HF_);
    gemm_tc<0, 0><<<dim3(1, M / 128), 256>>>(pt2, HF_, aw2, HF_, ab2, pre_act, ACT_, M, ACT_, HF_);
    sq_loss<<<4096, 256>>>(action, pre_act, (size_t)M * ACT_, 0);

    // ---- reward path ----
    gemm_tc<1, 1><<<dim3(HF_ / 128, M / 128), 256>>>(pt1 + 1024, G3_, rw1, HF_, rb1, pt2, HF_, M, HF_, HF_);
    gemv_rw<<<(M * 32 + 255) / 256, 256>>>(pt2, rw2, rb2, pre_rew, M);
    sq_loss<<<4096, 256>>>(action, pre_rew, (size_t)M * ACT_, 5);

    finalize_loss<<<1, 1>>>(out);
}

// round 15
// speedup vs baseline: 1.4164x; 1.4164x over previous
#include <cuda_runtime.h>
#include <math.h>
#include <stdint.h>

#define T_   512
#define B_   256
#define OBS_ 128
#define ACT_ 32
#define HID_ 512
#define HF_  512
#define IN_  160
#define G3_  1536

__device__ float g_X  [(size_t)T_ * B_ * IN_];
__device__ float g_gi [(size_t)T_ * B_ * G3_];
__device__ float g_gi0[(size_t)B_ * G3_];
__device__ float g_hs [(size_t)T_ * B_ * HID_];
__device__ float g_t1 [(size_t)T_ * B_ * G3_];
__device__ float g_t2 [(size_t)T_ * B_ * HF_];
__device__ float g_whi[(size_t)G3_ * HID_];
__device__ float g_wlo[(size_t)G3_ * HID_];
__device__ float g_wcat[(size_t)3 * HF_ * HID_];
__device__ float g_bcat[3 * HF_];
__device__ unsigned g_bar;
__device__ double g_acc;

__device__ __forceinline__ void split2(float x, uint32_t& hi, uint32_t& lo)
{
    uint32_t hb = __float_as_uint(x) & 0xFFFFE000u;
    hi = hb;
    lo = __float_as_uint(x - __uint_as_float(hb));
}

__device__ __forceinline__ void mma_tf32(float* c,
                                         uint32_t a0, uint32_t a1, uint32_t a2, uint32_t a3,
                                         uint32_t b0, uint32_t b1)
{
    asm volatile(
        "mma.sync.aligned.m16n8k8.row.col.f32.tf32.tf32.f32 "
        "{%0,%1,%2,%3}, {%4,%5,%6,%7}, {%8,%9}, {%0,%1,%2,%3};"
        : "+f"(c[0]), "+f"(c[1]), "+f"(c[2]), "+f"(c[3])
        : "r"(a0), "r"(a1), "r"(a2), "r"(a3), "r"(b0), "r"(b1));
}

// ---------- tensor-core GEMM: CTA 128x128, warp 64x32, BK=16 ----------
template <int ACTMODE, int ALIGNED>
__global__ void __launch_bounds__(256) gemm_tc(
    const float* __restrict__ A, int lda,
    const float* __restrict__ B, int ldb,
    const float* __restrict__ bias,
    float* __restrict__ C, int ldc,
    int M, int N, int K)
{
    __shared__ float As[2][16][136];
    __shared__ float Bs[2][16][136];

    const int bm = blockIdx.y * 128;
    const int bn = blockIdx.x * 128;
    const int tid  = threadIdx.x;
    const int warp = tid >> 5, lane = tid & 31;
    const int wm = (warp >> 2) * 64;
    const int wn = (warp & 3) * 32;
    const int g  = lane >> 2;
    const int tg = lane & 3;
    const int r0 = tid >> 2;
    const int q0 = (tid & 3) << 2;

    float acc[4][4][4];
#pragma unroll
    for (int mi = 0; mi < 4; mi++)
#pragma unroll
        for (int ni = 0; ni < 4; ni++)
#pragma unroll
            for (int r = 0; r < 4; r++) acc[mi][ni][r] = 0.f;

    const int niter = K >> 4;
    const float4 z4 = make_float4(0.f, 0.f, 0.f, 0.f);

    float4 sa0, sa1, sb0, sb1;
    sa0 = *(const float4*)(A + (size_t)(bm + r0) * lda + q0);
    sa1 = *(const float4*)(A + (size_t)(bm + r0 + 64) * lda + q0);
    sb0 = (bn + r0      < N) ? *(const float4*)(B + (size_t)(bn + r0) * ldb + q0)      : z4;
    sb1 = (bn + r0 + 64 < N) ? *(const float4*)(B + (size_t)(bn + r0 + 64) * ldb + q0) : z4;

    As[0][q0 + 0][r0] = sa0.x; As[0][q0 + 1][r0] = sa0.y;
    As[0][q0 + 2][r0] = sa0.z; As[0][q0 + 3][r0] = sa0.w;
    As[0][q0 + 0][r0 + 64] = sa1.x; As[0][q0 + 1][r0 + 64] = sa1.y;
    As[0][q0 + 2][r0 + 64] = sa1.z; As[0][q0 + 3][r0 + 64] = sa1.w;
    Bs[0][q0 + 0][r0] = sb0.x; Bs[0][q0 + 1][r0] = sb0.y;
    Bs[0][q0 + 2][r0] = sb0.z; Bs[0][q0 + 3][r0] = sb0.w;
    Bs[0][q0 + 0][r0 + 64] = sb1.x; Bs[0][q0 + 1][r0 + 64] = sb1.y;
    Bs[0][q0 + 2][r0 + 64] = sb1.z; Bs[0][q0 + 3][r0 + 64] = sb1.w;
    __syncthreads();

    for (int it = 0; it < niter; ++it) {
        const int buf = it & 1;
        const bool have_next = (it + 1 < niter);
        if (have_next) {
            const int k0 = (it + 1) << 4;
            sa0 = *(const float4*)(A + (size_t)(bm + r0) * lda + k0 + q0);
            sa1 = *(const float4*)(A + (size_t)(bm + r0 + 64) * lda + k0 + q0);
            sb0 = (bn + r0      < N) ? *(const float4*)(B + (size_t)(bn + r0) * ldb + k0 + q0)      : z4;
            sb1 = (bn + r0 + 64 < N) ? *(const float4*)(B + (size_t)(bn + r0 + 64) * ldb + k0 + q0) : z4;
        }

#pragma unroll
        for (int kk = 0; kk < 16; kk += 8) {
            uint32_t ah[4][4], al[4][4];
#pragma unroll
            for (int mi = 0; mi < 4; mi++) {
                const int m = wm + mi * 16 + g;
                split2(As[buf][kk + tg][m],         ah[mi][0], al[mi][0]);
                split2(As[buf][kk + tg][m + 8],     ah[mi][1], al[mi][1]);
                split2(As[buf][kk + tg + 4][m],     ah[mi][2], al[mi][2]);
                split2(As[buf][kk + tg + 4][m + 8], ah[mi][3], al[mi][3]);
            }
            uint32_t bh[4][2], bl[4][2];
#pragma unroll
            for (int ni = 0; ni < 4; ni++) {
                const int n = wn + ni * 8 + g;
                split2(Bs[buf][kk + tg][n],     bh[ni][0], bl[ni][0]);
                split2(Bs[buf][kk + tg + 4][n], bh[ni][1], bl[ni][1]);
            }
#pragma unroll
            for (int mi = 0; mi < 4; mi++)
#pragma unroll
                for (int ni = 0; ni < 4; ni++) {
                    float* c = acc[mi][ni];
                    mma_tf32(c, al[mi][0], al[mi][1], al[mi][2], al[mi][3],
                             bh[ni][0], bh[ni][1]);
                    mma_tf32(c, ah[mi][0], ah[mi][1], ah[mi][2], ah[mi][3],
                             bl[ni][0], bl[ni][1]);
                    mma_tf32(c, ah[mi][0], ah[mi][1], ah[mi][2], ah[mi][3],
                             bh[ni][0], bh[ni][1]);
                }
        }

        if (have_next) {
            const int nb = buf ^ 1;
            As[nb][q0 + 0][r0] = sa0.x; As[nb][q0 + 1][r0] = sa0.y;
            As[nb][q0 + 2][r0] = sa0.z; As[nb][q0 + 3][r0] = sa0.w;
            As[nb][q0 + 0][r0 + 64] = sa1.x; As[nb][q0 + 1][r0 + 64] = sa1.y;
            As[nb][q0 + 2][r0 + 64] = sa1.z; As[nb][q0 + 3][r0 + 64] = sa1.w;
            Bs[nb][q0 + 0][r0] = sb0.x; Bs[nb][q0 + 1][r0] = sb0.y;
            Bs[nb][q0 + 2][r0] = sb0.z; Bs[nb][q0 + 3][r0] = sb0.w;
            Bs[nb][q0 + 0][r0 + 64] = sb1.x; Bs[nb][q0 + 1][r0 + 64] = sb1.y;
            Bs[nb][q0 + 2][r0 + 64] = sb1.z; Bs[nb][q0 + 3][r0 + 64] = sb1.w;
            __syncthreads();
        }
    }

#pragma unroll
    for (int mi = 0; mi < 4; mi++) {
        const int row = bm + wm + mi * 16 + g;
#pragma unroll
        for (int ni = 0; ni < 4; ni++) {
            const int col = bn + wn + ni * 8 + tg * 2;
            if (col < N) {
                const float* c = acc[mi][ni];
                float v0 = c[0] + bias[col];
                float v1 = c[1] + bias[col + 1];
                float v2 = c[2] + bias[col];
                float v3 = c[3] + bias[col + 1];
                if (ACTMODE == 1) {
                    v0 = v0 > 0.f ? v0 : expm1f(v0);
                    v1 = v1 > 0.f ? v1 : expm1f(v1);
                    v2 = v2 > 0.f ? v2 : expm1f(v2);
                    v3 = v3 > 0.f ? v3 : expm1f(v3);
                }
                if (ALIGNED) {
                    *(float2*)(C + (size_t)row * ldc + col)       = make_float2(v0, v1);
                    *(float2*)(C + (size_t)(row + 8) * ldc + col) = make_float2(v2, v3);
                } else {
                    C[(size_t)row * ldc + col]           = v0;
                    C[(size_t)row * ldc + col + 1]       = v1;
                    C[(size_t)(row + 8) * ldc + col]     = v2;
                    C[(size_t)(row + 8) * ldc + col + 1] = v3;
                }
            }
        }
    }
}

// ---------------- weight presplit + concat ----------------
__global__ void split_w(const float* __restrict__ w, float* __restrict__ hi,
                        float* __restrict__ lo, int n)
{
    int i = blockIdx.x * blockDim.x + threadIdx.x;
    if (i >= n) return;
    float x = w[i];
    uint32_t hb = __float_as_uint(x) & 0xFFFFE000u;
    float h = __uint_as_float(hb);
    hi[i] = h;
    lo[i] = x - h;
}

__global__ void concat_w(const float* __restrict__ w0, const float* __restrict__ w1,
                         const float* __restrict__ w2,
                         const float* __restrict__ b0, const float* __restrict__ b1,
                         const float* __restrict__ b2)
{
    int i = blockIdx.x * blockDim.x + threadIdx.x;
    const int n = HF_ * HID_;
    if (i < n) {
        g_wcat[i]         = w0[i];
        g_wcat[n + i]     = w1[i];
        g_wcat[2 * n + i] = w2[i];
    }
    if (i < HF_) {
        g_bcat[i]           = b0[i];
        g_bcat[HF_ + i]     = b1[i];
        g_bcat[2 * HF_ + i] = b2[i];
    }
}

// ============ persistent tensor-core GRU, conflict-free W staging ============
// smem (floats): Hs[2][64][68] at 0 (4352/buf); W[2][hi/lo][48][68] at 8704
// (6528/buf, lo at +3264). gh staging aliases Hs buf0. Total 21760 fl = 87040 B.
#define GRU_SMEM 87040
#define HS_STR 68
#define WN_STR 68
#define GH_STR 52
#define NCTAS 128u
__global__ void __launch_bounds__(256) gru_persist(
    const float* __restrict__ whi, const float* __restrict__ wlo,
    const float* __restrict__ b_hh)
{
    extern __shared__ float sm[];
    const int n0 = blockIdx.x * 16;
    const int m0 = blockIdx.y * 64;
    const int tid  = threadIdx.x;
    const int warp = tid >> 5, lane = tid & 31;
    const int wm = (warp & 3) * 16;
    const int wn = (warp >> 2) * 24;
    const int g  = lane >> 2;
    const int tg = lane & 3;
    const int hr = tid >> 2;
    const int hc4 = (tid & 3) << 2;

    float4 sh[4], sw[6];

#define GRU_LDG(H, K0)                                                         \
    do {                                                                       \
        _Pragma("unroll")                                                      \
        for (int s = 0; s < 4; s++)                                            \
            sh[s] = *(const float4*)((H) + (size_t)(m0 + hr) * HID_ + (K0) + s * 16 + hc4); \
        _Pragma("unroll")                                                      \
        for (int s = 0; s < 6; s++) {                                          \
            int f = tid + (s << 8);                                            \
            int i = f >> 4;                                                    \
            int c4 = (f & 15) << 2;                                            \
            int i48 = (i < 48) ? i : i - 48;                                   \
            const float* src = (i < 48) ? whi : wlo;                           \
            int grow = (i48 >> 4) * HID_ + n0 + (i48 & 15);                    \
            sw[s] = *(const float4*)(src + (size_t)grow * HID_ + (K0) + c4);   \
        }                                                                      \
    } while (0)

// W stored n-major [n][k], stride 68 (== 4 mod 32): STS.128 per float4
// (near conflict-free), mainloop loads bank = 4g + tg + const -> conflict-free.
#define GRU_STS(BUF)                                                           \
    do {                                                                       \
        float* hp = sm + (BUF) * 4352;                                         \
        _Pragma("unroll")                                                      \
        for (int s = 0; s < 4; s++) {                                          \
            int kb = s * 16 + hc4;                                             \
            hp[(kb + 0) * HS_STR + hr] = sh[s].x;                              \
            hp[(kb + 1) * HS_STR + hr] = sh[s].y;                              \
            hp[(kb + 2) * HS_STR + hr] = sh[s].z;                              \
            hp[(kb + 3) * HS_STR + hr] = sh[s].w;                              \
        }                                                                      \
        _Pragma("unroll")                                                      \
        for (int s = 0; s < 6; s++) {                                          \
            int f = tid + (s << 8);                                            \
            int i = f >> 4;                                                    \
            int c4 = (f & 15) << 2;                                            \
            int i48 = (i < 48) ? i : i - 48;                                   \
            float* wp = sm + 8704 + (BUF) * 6528 + ((i < 48) ? 0 : 3264);      \
            *(float4*)(wp + i48 * WN_STR + c4) = sw[s];                        \
        }                                                                      \
    } while (0)

    for (int t = 0; t < T_ - 1; ++t) {
        const float* h  = g_hs + (size_t)t * B_ * HID_;
        const float* gi = g_gi + (size_t)t * B_ * G3_;
        float* h_next   = g_hs + (size_t)(t + 1) * B_ * HID_;

        float acc[3][4];
#pragma unroll
        for (int ni = 0; ni < 3; ni++)
#pragma unroll
            for (int r = 0; r < 4; r++) acc[ni][r] = 0.f;

        GRU_LDG(h, 0);
        GRU_STS(0);
        __syncthreads();

        const int NIT = HID_ / 64;   // 8
        for (int it = 0; it < NIT; ++it) {
            const int buf = it & 1;
            const float* Hb = sm + buf * 4352;
            const float* Wh = sm + 8704 + buf * 6528;
            const float* Wl = Wh + 3264;
            const bool have_next = (it + 1 < NIT);
            if (have_next) GRU_LDG(h, (it + 1) * 64);

#pragma unroll
            for (int kk = 0; kk < 64; kk += 8) {
                uint32_t ah[4], al[4];
                split2(Hb[(kk + tg) * HS_STR + wm + g],         ah[0], al[0]);
                split2(Hb[(kk + tg) * HS_STR + wm + g + 8],     ah[1], al[1]);
                split2(Hb[(kk + tg + 4) * HS_STR + wm + g],     ah[2], al[2]);
                split2(Hb[(kk + tg + 4) * HS_STR + wm + g + 8], ah[3], al[3]);
#pragma unroll
                for (int ni = 0; ni < 3; ni++) {
                    const int n = wn + ni * 8 + g;
                    uint32_t bh0 = __float_as_uint(Wh[n * WN_STR + kk + tg]);
                    uint32_t bh1 = __float_as_uint(Wh[n * WN_STR + kk + tg + 4]);
                    uint32_t bl0 = __float_as_uint(Wl[n * WN_STR + kk + tg]);
                    uint32_t bl1 = __float_as_uint(Wl[n * WN_STR + kk + tg + 4]);
                    float* c = acc[ni];
                    mma_tf32(c, al[0], al[1], al[2], al[3], bh0, bh1);
                    mma_tf32(c, ah[0], ah[1], ah[2], ah[3], bl0, bl1);
                    mma_tf32(c, ah[0], ah[1], ah[2], ah[3], bh0, bh1);
                }
            }

            if (have_next) {
                GRU_STS(buf ^ 1);
                __syncthreads();
            }
        }

        // stage gh into Hs buf0 region (last compute used buf1 regions)
        float* gh = sm;
#pragma unroll
        for (int ni = 0; ni < 3; ni++) {
            const int col = wn + ni * 8 + tg * 2;
            gh[(wm + g) * GH_STR + col]         = acc[ni][0];
            gh[(wm + g) * GH_STR + col + 1]     = acc[ni][1];
            gh[(wm + g + 8) * GH_STR + col]     = acc[ni][2];
            gh[(wm + g + 8) * GH_STR + col + 1] = acc[ni][3];
        }
        __syncthreads();

        {
            const int ml = tid >> 2;
            const int nb = (tid & 3) << 2;
            const float* gir = gi + (size_t)(m0 + ml) * G3_;
            const float* hrow = h + (size_t)(m0 + ml) * HID_;
            float* orow = h_next + (size_t)(m0 + ml) * HID_;
#pragma unroll
            for (int j = 0; j < 4; j++) {
                const int nl = nb + j;
                const int n = n0 + nl;
                float ghr = gh[ml * GH_STR + nl]      + b_hh[n];
                float ghz = gh[ml * GH_STR + 16 + nl] + b_hh[512 + n];
                float ghn = gh[ml * GH_STR + 32 + nl] + b_hh[1024 + n];
                float r  = 1.f / (1.f + expf(-(gir[n] + ghr)));
                float z  = 1.f / (1.f + expf(-(gir[512 + n] + ghz)));
                float nn = tanhf(gir[1024 + n] + r * ghn);
                orow[n] = (1.f - z) * nn + z * hrow[n];
            }
        }

        if (t < T_ - 2) {
            __threadfence();
            __syncthreads();
            if (tid == 0) {
                atomicAdd(&g_bar, 1u);
                const unsigned target = NCTAS * (unsigned)(t + 1);
                while (*(volatile unsigned*)&g_bar < target) { }
            }
            __syncthreads();
            __threadfence();
        }
    }
}

// ---------------- pack X ----------------
__global__ void pack_x(const float* __restrict__ obs, const float* __restrict__ act)
{
    size_t i = (size_t)blockIdx.x * blockDim.x + threadIdx.x;
    const size_t n = (size_t)T_ * B_ * IN_;
    if (i >= n) return;
    size_t row = i / IN_;
    int c = (int)(i % IN_);
    g_X[i] = (c < OBS_) ? obs[row * OBS_ + c] : act[row * ACT_ + (c - OBS_)];
}

__global__ void h0_kernel(const float* __restrict__ b_hh)
{
    int i = blockIdx.x * blockDim.x + threadIdx.x;
    if (i == 0) g_bar = 0u;
    if (i >= B_ * HID_) return;
    int m = i >> 9, j = i & 511;
    const float* gr = g_gi0 + (size_t)m * G3_;
    float r  = 1.f / (1.f + expf(-(gr[j]        + b_hh[j])));
    float z  = 1.f / (1.f + expf(-(gr[512 + j]  + b_hh[512 + j])));
    float nn = tanhf(gr[1024 + j] + r * b_hh[1024 + j]);
    g_hs[i] = (1.f - z) * nn;
}

__global__ void gemv_rw(const float* __restrict__ A, const float* __restrict__ w,
                        const float* __restrict__ b, float* __restrict__ out, int M)
{
    int gw = (int)(((size_t)blockIdx.x * blockDim.x + threadIdx.x) >> 5);
    int lane = threadIdx.x & 31;
    if (gw >= M) return;
    const float* row = A + (size_t)gw * HF_;
    float s = 0.f;
#pragma unroll
    for (int k = lane; k < HF_; k += 32) s = fmaf(row[k], w[k], s);
#pragma unroll
    for (int o = 16; o; o >>= 1) s += __shfl_xor_sync(0xffffffffu, s, o);
    if (lane == 0) out[gw] = s + b[0];
}

__global__ void loss_init() { g_acc = 0.0; }

__global__ void sq_loss(const float* __restrict__ x, const float* __restrict__ mu,
                        size_t n, int shift)
{
    float s = 0.f;
    for (size_t i = (size_t)blockIdx.x * blockDim.x + threadIdx.x; i < n;
         i += (size_t)gridDim.x * blockDim.x) {
        float d = x[i] - mu[i >> shift];
        s = fmaf(0.5f * d, d, s);
    }
#pragma unroll
    for (int o = 16; o; o >>= 1) s += __shfl_xor_sync(0xffffffffu, s, o);
    __shared__ float ws[8];
    int lane = threadIdx.x & 31, w = threadIdx.x >> 5;
    if (lane == 0) ws[w] = s;
    __syncthreads();
    if (w == 0) {
        s = lane < (blockDim.x >> 5) ? ws[lane] : 0.f;
#pragma unroll
        for (int o = 4; o; o >>= 1) s += __shfl_xor_sync(0xffu, s, o);
        if (lane == 0) atomicAdd(&g_acc, (double)s);
    }
}

__global__ void finalize_loss(float* out)
{
    const double LOG2PI = 1.8378770664093453;
    out[0] = (float)(g_acc / (double)((size_t)T_ * B_) +
                     0.5 * LOG2PI * (double)(OBS_ + ACT_ + ACT_));
}

// ---------------- launch ----------------
extern "C" void kernel_launch(void* const* d_in, const int* in_sizes, int n_in,
                              void* d_out, int out_size)
{
    const float* obs    = (const float*)d_in[0];
    const float* action = (const float*)d_in[1];
    const float* w_ih = (const float*)d_in[3];
    const float* w_hh = (const float*)d_in[4];
    const float* b_ih = (const float*)d_in[5];
    const float* b_hh = (const float*)d_in[6];
    const float *ow0 = (const float*)d_in[7],  *ob0 = (const float*)d_in[8];
    const float *ow1 = (const float*)d_in[9],  *ob1 = (const float*)d_in[10];
    const float *ow2 = (const float*)d_in[11], *ob2 = (const float*)d_in[12];
    const float *aw0 = (const float*)d_in[13], *ab0 = (const float*)d_in[14];
    const float *aw1 = (const float*)d_in[15], *ab1 = (const float*)d_in[16];
    const float *aw2 = (const float*)d_in[17], *ab2 = (const float*)d_in[18];
    const float *rw0 = (const float*)d_in[19], *rb0 = (const float*)d_in[20];
    const float *rw1 = (const float*)d_in[21], *rb1 = (const float*)d_in[22];
    const float *rw2 = (const float*)d_in[23], *rb2 = (const float*)d_in[24];

    float* out = (float*)d_out;
    float* pre_obs = out + 1;
    float* pre_act = pre_obs + (size_t)T_ * B_ * OBS_;
    float* pre_rew = pre_act + (size_t)T_ * B_ * ACT_;

    float *pX, *pgi, *pgi0, *phs, *pt1, *pt2, *pwhi, *pwlo, *pwcat, *pbcat;
    cudaGetSymbolAddress((void**)&pX,   g_X);
    cudaGetSymbolAddress((void**)&pgi,  g_gi);
    cudaGetSymbolAddress((void**)&pgi0, g_gi0);
    cudaGetSymbolAddress((void**)&phs,  g_hs);
    cudaGetSymbolAddress((void**)&pt1,  g_t1);
    cudaGetSymbolAddress((void**)&pt2,  g_t2);
    cudaGetSymbolAddress((void**)&pwhi, g_whi);
    cudaGetSymbolAddress((void**)&pwlo, g_wlo);
    cudaGetSymbolAddress((void**)&pwcat, g_wcat);
    cudaGetSymbolAddress((void**)&pbcat, g_bcat);

    static int smem_set = 0;
    if (!smem_set) {
        cudaFuncSetAttribute(gru_persist, cudaFuncAttributeMaxDynamicSharedMemorySize, GRU_SMEM);
        smem_set = 1;
    }

    const int M = T_ * B_;  // 131072

    loss_init<<<1, 1>>>();

    {
        size_t n = (size_t)T_ * B_ * IN_;
        pack_x<<<(unsigned)((n + 255) / 256), 256>>>(obs, action);
    }

    split_w<<<(G3_ * HID_ + 255) / 256, 256>>>(w_hh, pwhi, pwlo, G3_ * HID_);
    concat_w<<<(HF_ * HID_ + 255) / 256, 256>>>(ow0, aw0, rw0, ob0, ab0, rb0);

    gemm_tc<0, 1><<<dim3(G3_ / 128, M / 128), 256>>>(
        pX, IN_, w_ih, IN_, b_ih, pgi, G3_, M, G3_, IN_);

    gemm_tc<0, 1><<<dim3(G3_ / 128, B_ / 128), 256>>>(
        obs, OBS_, w_ih, IN_, b_ih, pgi0, G3_, B_, G3_, OBS_);

    h0_kernel<<<(B_ * HID_ + 255) / 256, 256>>>(b_hh);

    gru_persist<<<dim3(HID_ / 16, B_ / 64), 256, GRU_SMEM>>>(pwhi, pwlo, b_hh);

    // ---- fused MLP layer 1 (obs|act|rew): [M,512] -> [M,1536] ----
    gemm_tc<1, 1><<<dim3(G3_ / 128, M / 128), 256>>>(
        phs, HID_, pwcat, HID_, pbcat, pt1, G3_, M, G3_, HID_);

    // ---- obs path ----
    gemm_tc<1, 1><<<dim3(HF_ / 128, M / 128), 256>>>(pt1, G3_, ow1, HF_, ob1, pt2, HF_, M, HF_, HF_);
    gemm_tc<0, 0><<<dim3(1, M / 128), 256>>>(pt2, HF_, ow2, HF_, ob2, pre_obs, OBS_, M, OBS_, HF_);
    sq_loss<<<4096, 256>>>(obs, pre_obs, (size_t)M * OBS_, 0);

    // ---- action path ----
    gemm_tc<1, 1><<<dim3(HF_ / 128, M / 128), 256>>>(pt1 + 512, G3_, aw1, HF_, ab1, pt2, HF_, M, HF_, HF_);
    gemm_tc<0, 0><<<dim3(1, M / 128), 256>>>(pt2, HF_, aw2, HF_, ab2, pre_act, ACT_, M, ACT_, HF_);
    sq_loss<<<4096, 256>>>(action, pre_act, (size_t)M * ACT_, 0);

    // ---- reward path ----
    gemm_tc<1, 1><<<dim3(HF_ / 128, M / 128), 256>>>(pt1 + 1024, G3_, rw1, HF_, rb1, pt2, HF_, M, HF_, HF_);
    gemv_rw<<<(M * 32 + 255) / 256, 256>>>(pt2, rw2, rb2, pre_rew, M);
    sq_loss<<<4096, 256>>>(action, pre_rew, (size_t)M * ACT_, 5);

    finalize_loss<<<1, 1>>>(out);
}

// round 16
// speedup vs baseline: 1.5185x; 1.0721x over previous
#include <cuda_runtime.h>
#include <math.h>
#include <stdint.h>

#define T_   512
#define B_   256
#define OBS_ 128
#define ACT_ 32
#define HID_ 512
#define HF_  512
#define IN_  160
#define G3_  1536

__device__ float g_X  [(size_t)T_ * B_ * IN_];
__device__ float g_gi [(size_t)T_ * B_ * G3_];
__device__ float g_gi0[(size_t)B_ * G3_];
__device__ float g_hs [(size_t)T_ * B_ * HID_];
__device__ float g_t1 [(size_t)T_ * B_ * G3_];
__device__ float g_t2 [(size_t)T_ * B_ * HF_];
__device__ float g_whi[(size_t)G3_ * HID_];
__device__ float g_wlo[(size_t)G3_ * HID_];
__device__ float g_wcat[(size_t)3 * HF_ * HID_];
__device__ float g_bcat[3 * HF_];
__device__ unsigned g_bar;
__device__ double g_acc;

__device__ __forceinline__ void split2(float x, uint32_t& hi, uint32_t& lo)
{
    uint32_t hb = __float_as_uint(x) & 0xFFFFE000u;
    hi = hb;
    lo = __float_as_uint(x - __uint_as_float(hb));
}

__device__ __forceinline__ void mma_tf32(float* c,
                                         uint32_t a0, uint32_t a1, uint32_t a2, uint32_t a3,
                                         uint32_t b0, uint32_t b1)
{
    asm volatile(
        "mma.sync.aligned.m16n8k8.row.col.f32.tf32.tf32.f32 "
        "{%0,%1,%2,%3}, {%4,%5,%6,%7}, {%8,%9}, {%0,%1,%2,%3};"
        : "+f"(c[0]), "+f"(c[1]), "+f"(c[2]), "+f"(c[3])
        : "r"(a0), "r"(a1), "r"(a2), "r"(a3), "r"(b0), "r"(b1));
}

// ---------- tensor-core GEMM: CTA 128x128, warp 64x32, BK=16 ----------
template <int ACTMODE, int ALIGNED>
__global__ void __launch_bounds__(256) gemm_tc(
    const float* __restrict__ A, int lda,
    const float* __restrict__ B, int ldb,
    const float* __restrict__ bias,
    float* __restrict__ C, int ldc,
    int M, int N, int K)
{
    __shared__ float As[2][16][136];
    __shared__ float Bs[2][16][136];

    const int bm = blockIdx.y * 128;
    const int bn = blockIdx.x * 128;
    const int tid  = threadIdx.x;
    const int warp = tid >> 5, lane = tid & 31;
    const int wm = (warp >> 2) * 64;
    const int wn = (warp & 3) * 32;
    const int g  = lane >> 2;
    const int tg = lane & 3;
    const int r0 = tid >> 2;
    const int q0 = (tid & 3) << 2;

    float acc[4][4][4];
#pragma unroll
    for (int mi = 0; mi < 4; mi++)
#pragma unroll
        for (int ni = 0; ni < 4; ni++)
#pragma unroll
            for (int r = 0; r < 4; r++) acc[mi][ni][r] = 0.f;

    const int niter = K >> 4;
    const float4 z4 = make_float4(0.f, 0.f, 0.f, 0.f);

    float4 sa0, sa1, sb0, sb1;
    sa0 = *(const float4*)(A + (size_t)(bm + r0) * lda + q0);
    sa1 = *(const float4*)(A + (size_t)(bm + r0 + 64) * lda + q0);
    sb0 = (bn + r0      < N) ? *(const float4*)(B + (size_t)(bn + r0) * ldb + q0)      : z4;
    sb1 = (bn + r0 + 64 < N) ? *(const float4*)(B + (size_t)(bn + r0 + 64) * ldb + q0) : z4;

    As[0][q0 + 0][r0] = sa0.x; As[0][q0 + 1][r0] = sa0.y;
    As[0][q0 + 2][r0] = sa0.z; As[0][q0 + 3][r0] = sa0.w;
    As[0][q0 + 0][r0 + 64] = sa1.x; As[0][q0 + 1][r0 + 64] = sa1.y;
    As[0][q0 + 2][r0 + 64] = sa1.z; As[0][q0 + 3][r0 + 64] = sa1.w;
    Bs[0][q0 + 0][r0] = sb0.x; Bs[0][q0 + 1][r0] = sb0.y;
    Bs[0][q0 + 2][r0] = sb0.z; Bs[0][q0 + 3][r0] = sb0.w;
    Bs[0][q0 + 0][r0 + 64] = sb1.x; Bs[0][q0 + 1][r0 + 64] = sb1.y;
    Bs[0][q0 + 2][r0 + 64] = sb1.z; Bs[0][q0 + 3][r0 + 64] = sb1.w;
    __syncthreads();

    for (int it = 0; it < niter; ++it) {
        const int buf = it & 1;
        const bool have_next = (it + 1 < niter);
        if (have_next) {
            const int k0 = (it + 1) << 4;
            sa0 = *(const float4*)(A + (size_t)(bm + r0) * lda + k0 + q0);
            sa1 = *(const float4*)(A + (size_t)(bm + r0 + 64) * lda + k0 + q0);
            sb0 = (bn + r0      < N) ? *(const float4*)(B + (size_t)(bn + r0) * ldb + k0 + q0)      : z4;
            sb1 = (bn + r0 + 64 < N) ? *(const float4*)(B + (size_t)(bn + r0 + 64) * ldb + k0 + q0) : z4;
        }

#pragma unroll
        for (int kk = 0; kk < 16; kk += 8) {
            uint32_t ah[4][4], al[4][4];
#pragma unroll
            for (int mi = 0; mi < 4; mi++) {
                const int m = wm + mi * 16 + g;
                split2(As[buf][kk + tg][m],         ah[mi][0], al[mi][0]);
                split2(As[buf][kk + tg][m + 8],     ah[mi][1], al[mi][1]);
                split2(As[buf][kk + tg + 4][m],     ah[mi][2], al[mi][2]);
                split2(As[buf][kk + tg + 4][m + 8], ah[mi][3], al[mi][3]);
            }
            uint32_t bh[4][2], bl[4][2];
#pragma unroll
            for (int ni = 0; ni < 4; ni++) {
                const int n = wn + ni * 8 + g;
                split2(Bs[buf][kk + tg][n],     bh[ni][0], bl[ni][0]);
                split2(Bs[buf][kk + tg + 4][n], bh[ni][1], bl[ni][1]);
            }
#pragma unroll
            for (int mi = 0; mi < 4; mi++)
#pragma unroll
                for (int ni = 0; ni < 4; ni++) {
                    float* c = acc[mi][ni];
                    mma_tf32(c, al[mi][0], al[mi][1], al[mi][2], al[mi][3],
                             bh[ni][0], bh[ni][1]);
                    mma_tf32(c, ah[mi][0], ah[mi][1], ah[mi][2], ah[mi][3],
                             bl[ni][0], bl[ni][1]);
                    mma_tf32(c, ah[mi][0], ah[mi][1], ah[mi][2], ah[mi][3],
                             bh[ni][0], bh[ni][1]);
                }
        }

        if (have_next) {
            const int nb = buf ^ 1;
            As[nb][q0 + 0][r0] = sa0.x; As[nb][q0 + 1][r0] = sa0.y;
            As[nb][q0 + 2][r0] = sa0.z; As[nb][q0 + 3][r0] = sa0.w;
            As[nb][q0 + 0][r0 + 64] = sa1.x; As[nb][q0 + 1][r0 + 64] = sa1.y;
            As[nb][q0 + 2][r0 + 64] = sa1.z; As[nb][q0 + 3][r0 + 64] = sa1.w;
            Bs[nb][q0 + 0][r0] = sb0.x; Bs[nb][q0 + 1][r0] = sb0.y;
            Bs[nb][q0 + 2][r0] = sb0.z; Bs[nb][q0 + 3][r0] = sb0.w;
            Bs[nb][q0 + 0][r0 + 64] = sb1.x; Bs[nb][q0 + 1][r0 + 64] = sb1.y;
            Bs[nb][q0 + 2][r0 + 64] = sb1.z; Bs[nb][q0 + 3][r0 + 64] = sb1.w;
            __syncthreads();
        }
    }

#pragma unroll
    for (int mi = 0; mi < 4; mi++) {
        const int row = bm + wm + mi * 16 + g;
#pragma unroll
        for (int ni = 0; ni < 4; ni++) {
            const int col = bn + wn + ni * 8 + tg * 2;
            if (col < N) {
                const float* c = acc[mi][ni];
                float v0 = c[0] + bias[col];
                float v1 = c[1] + bias[col + 1];
                float v2 = c[2] + bias[col];
                float v3 = c[3] + bias[col + 1];
                if (ACTMODE == 1) {
                    v0 = v0 > 0.f ? v0 : expm1f(v0);
                    v1 = v1 > 0.f ? v1 : expm1f(v1);
                    v2 = v2 > 0.f ? v2 : expm1f(v2);
                    v3 = v3 > 0.f ? v3 : expm1f(v3);
                }
                if (ALIGNED) {
                    *(float2*)(C + (size_t)row * ldc + col)       = make_float2(v0, v1);
                    *(float2*)(C + (size_t)(row + 8) * ldc + col) = make_float2(v2, v3);
                } else {
                    C[(size_t)row * ldc + col]           = v0;
                    C[(size_t)row * ldc + col + 1]       = v1;
                    C[(size_t)(row + 8) * ldc + col]     = v2;
                    C[(size_t)(row + 8) * ldc + col + 1] = v3;
                }
            }
        }
    }
}

// ---------------- weight presplit + concat ----------------
__global__ void split_w(const float* __restrict__ w, float* __restrict__ hi,
                        float* __restrict__ lo, int n)
{
    int i = blockIdx.x * blockDim.x + threadIdx.x;
    if (i >= n) return;
    float x = w[i];
    uint32_t hb = __float_as_uint(x) & 0xFFFFE000u;
    float h = __uint_as_float(hb);
    hi[i] = h;
    lo[i] = x - h;
}

__global__ void concat_w(const float* __restrict__ w0, const float* __restrict__ w1,
                         const float* __restrict__ w2,
                         const float* __restrict__ b0, const float* __restrict__ b1,
                         const float* __restrict__ b2)
{
    int i = blockIdx.x * blockDim.x + threadIdx.x;
    const int n = HF_ * HID_;
    if (i < n) {
        g_wcat[i]         = w0[i];
        g_wcat[n + i]     = w1[i];
        g_wcat[2 * n + i] = w2[i];
    }
    if (i < HF_) {
        g_bcat[i]           = b0[i];
        g_bcat[HF_ + i]     = b1[i];
        g_bcat[2 * HF_ + i] = b2[i];
    }
}

// ============ persistent tensor-core GRU, W RESIDENT in smem ============
// smem (floats): Wh[48][516] at 0 (24768), Wl[48][516] at 24768, Hs[64][68] at
// 49536 (4352; gh[64][52] aliases it). Total 53888 floats = 215552 B (1 CTA/SM).
// W loaded ONCE before the t-loop; per step only H is staged.
#define GRU_SMEM 215552
#define WK_STR 516
#define HS_STR 68
#define GH_STR 52
#define NCTAS 128u
__global__ void __launch_bounds__(256) gru_persist(
    const float* __restrict__ whi, const float* __restrict__ wlo,
    const float* __restrict__ b_hh)
{
    extern __shared__ float sm[];
    float* Wh = sm;                 // [48][516]
    float* Wl = sm + 48 * WK_STR;   // [48][516]
    float* Hs = sm + 96 * WK_STR;   // [64 k][68 m] (single buffer)

    const int n0 = blockIdx.x * 16;
    const int m0 = blockIdx.y * 64;
    const int tid  = threadIdx.x;
    const int warp = tid >> 5, lane = tid & 31;
    const int wm = (warp & 3) * 16;
    const int wn = (warp >> 2) * 24;
    const int g  = lane >> 2;
    const int tg = lane & 3;
    const int hr = tid >> 2;
    const int hc4 = (tid & 3) << 2;

    // ---- one-time W load (hi+lo), n-major [n][k], stride 516 (== 4 mod 32) ----
    for (int f = tid; f < 6144; f += 256) {
        int r  = f >> 7;             // local row 0..47 (gate*16 + nloc)
        int c4 = (f & 127) << 2;     // k col 0..508
        int grow = (r >> 4) * HID_ + n0 + (r & 15);
        *(float4*)(Wh + r * WK_STR + c4) = *(const float4*)(whi + (size_t)grow * HID_ + c4);
        *(float4*)(Wl + r * WK_STR + c4) = *(const float4*)(wlo + (size_t)grow * HID_ + c4);
    }
    __syncthreads();

    float4 sh[4];

#define GRU_LDH(H, K0)                                                         \
    do {                                                                       \
        _Pragma("unroll")                                                      \
        for (int s = 0; s < 4; s++)                                            \
            sh[s] = *(const float4*)((H) + (size_t)(m0 + hr) * HID_ + (K0) + s * 16 + hc4); \
    } while (0)

#define GRU_STH()                                                              \
    do {                                                                       \
        _Pragma("unroll")                                                      \
        for (int s = 0; s < 4; s++) {                                          \
            int kb = s * 16 + hc4;                                             \
            Hs[(kb + 0) * HS_STR + hr] = sh[s].x;                              \
            Hs[(kb + 1) * HS_STR + hr] = sh[s].y;                              \
            Hs[(kb + 2) * HS_STR + hr] = sh[s].z;                              \
            Hs[(kb + 3) * HS_STR + hr] = sh[s].w;                              \
        }                                                                      \
    } while (0)

    for (int t = 0; t < T_ - 1; ++t) {
        const float* h  = g_hs + (size_t)t * B_ * HID_;
        const float* gi = g_gi + (size_t)t * B_ * G3_;
        float* h_next   = g_hs + (size_t)(t + 1) * B_ * HID_;

        float acc[3][4];
#pragma unroll
        for (int ni = 0; ni < 3; ni++)
#pragma unroll
            for (int r = 0; r < 4; r++) acc[ni][r] = 0.f;

        GRU_LDH(h, 0);
        GRU_STH();
        __syncthreads();

        const int NIT = HID_ / 64;   // 8
        for (int it = 0; it < NIT; ++it) {
            const bool have_next = (it + 1 < NIT);
            if (have_next) GRU_LDH(h, (it + 1) * 64);
            const int kb0 = it * 64;

#pragma unroll
            for (int kk = 0; kk < 64; kk += 8) {
                uint32_t ah[4], al[4];
                split2(Hs[(kk + tg) * HS_STR + wm + g],         ah[0], al[0]);
                split2(Hs[(kk + tg) * HS_STR + wm + g + 8],     ah[1], al[1]);
                split2(Hs[(kk + tg + 4) * HS_STR + wm + g],     ah[2], al[2]);
                split2(Hs[(kk + tg + 4) * HS_STR + wm + g + 8], ah[3], al[3]);
#pragma unroll
                for (int ni = 0; ni < 3; ni++) {
                    const int n = wn + ni * 8 + g;
                    uint32_t bh0 = __float_as_uint(Wh[n * WK_STR + kb0 + kk + tg]);
                    uint32_t bh1 = __float_as_uint(Wh[n * WK_STR + kb0 + kk + tg + 4]);
                    uint32_t bl0 = __float_as_uint(Wl[n * WK_STR + kb0 + kk + tg]);
                    uint32_t bl1 = __float_as_uint(Wl[n * WK_STR + kb0 + kk + tg + 4]);
                    float* c = acc[ni];
                    mma_tf32(c, al[0], al[1], al[2], al[3], bh0, bh1);
                    mma_tf32(c, ah[0], ah[1], ah[2], ah[3], bl0, bl1);
                    mma_tf32(c, ah[0], ah[1], ah[2], ah[3], bh0, bh1);
                }
            }

            if (have_next) {
                __syncthreads();   // all warps done reading Hs chunk
                GRU_STH();
                __syncthreads();   // Hs chunk it+1 visible
            }
        }

        // stage gh aliasing Hs (all reads of Hs done)
        __syncthreads();
        float* gh = Hs;
#pragma unroll
        for (int ni = 0; ni < 3; ni++) {
            const int col = wn + ni * 8 + tg * 2;
            gh[(wm + g) * GH_STR + col]         = acc[ni][0];
            gh[(wm + g) * GH_STR + col + 1]     = acc[ni][1];
            gh[(wm + g + 8) * GH_STR + col]     = acc[ni][2];
            gh[(wm + g + 8) * GH_STR + col + 1] = acc[ni][3];
        }
        __syncthreads();

        {
            const int ml = tid >> 2;
            const int nb = (tid & 3) << 2;
            const float* gir = gi + (size_t)(m0 + ml) * G3_;
            const float* hrow = h + (size_t)(m0 + ml) * HID_;
            float* orow = h_next + (size_t)(m0 + ml) * HID_;
#pragma unroll
            for (int j = 0; j < 4; j++) {
                const int nl = nb + j;
                const int n = n0 + nl;
                float ghr = gh[ml * GH_STR + nl]      + b_hh[n];
                float ghz = gh[ml * GH_STR + 16 + nl] + b_hh[512 + n];
                float ghn = gh[ml * GH_STR + 32 + nl] + b_hh[1024 + n];
                float r  = 1.f / (1.f + expf(-(gir[n] + ghr)));
                float z  = 1.f / (1.f + expf(-(gir[512 + n] + ghz)));
                float nn = tanhf(gir[1024 + n] + r * ghn);
                orow[n] = (1.f - z) * nn + z * hrow[n];
            }
        }

        if (t < T_ - 2) {
            __threadfence();
            __syncthreads();
            if (tid == 0) {
                atomicAdd(&g_bar, 1u);
                const unsigned target = NCTAS * (unsigned)(t + 1);
                while (*(volatile unsigned*)&g_bar < target) { }
            }
            __syncthreads();
            __threadfence();
        }
    }
}

// ---------------- pack X ----------------
__global__ void pack_x(const float* __restrict__ obs, const float* __restrict__ act)
{
    size_t i = (size_t)blockIdx.x * blockDim.x + threadIdx.x;
    const size_t n = (size_t)T_ * B_ * IN_;
    if (i >= n) return;
    size_t row = i / IN_;
    int c = (int)(i % IN_);
    g_X[i] = (c < OBS_) ? obs[row * OBS_ + c] : act[row * ACT_ + (c - OBS_)];
}

__global__ void h0_kernel(const float* __restrict__ b_hh)
{
    int i = blockIdx.x * blockDim.x + threadIdx.x;
    if (i == 0) g_bar = 0u;
    if (i >= B_ * HID_) return;
    int m = i >> 9, j = i & 511;
    const float* gr = g_gi0 + (size_t)m * G3_;
    float r  = 1.f / (1.f + expf(-(gr[j]        + b_hh[j])));
    float z  = 1.f / (1.f + expf(-(gr[512 + j]  + b_hh[512 + j])));
    float nn = tanhf(gr[1024 + j] + r * b_hh[1024 + j]);
    g_hs[i] = (1.f - z) * nn;
}

__global__ void gemv_rw(const float* __restrict__ A, const float* __restrict__ w,
                        const float* __restrict__ b, float* __restrict__ out, int M)
{
    int gw = (int)(((size_t)blockIdx.x * blockDim.x + threadIdx.x) >> 5);
    int lane = threadIdx.x & 31;
    if (gw >= M) return;
    const float* row = A + (size_t)gw * HF_;
    float s = 0.f;
#pragma unroll
    for (int k = lane; k < HF_; k += 32) s = fmaf(row[k], w[k], s);
#pragma unroll
    for (int o = 16; o; o >>= 1) s += __shfl_xor_sync(0xffffffffu, s, o);
    if (lane == 0) out[gw] = s + b[0];
}

__global__ void loss_init() { g_acc = 0.0; }

__global__ void sq_loss(const float* __restrict__ x, const float* __restrict__ mu,
                        size_t n, int shift)
{
    float s = 0.f;
    for (size_t i = (size_t)blockIdx.x * blockDim.x + threadIdx.x; i < n;
         i += (size_t)gridDim.x * blockDim.x) {
        float d = x[i] - mu[i >> shift];
        s = fmaf(0.5f * d, d, s);
    }
#pragma unroll
    for (int o = 16; o; o >>= 1) s += __shfl_xor_sync(0xffffffffu, s, o);
    __shared__ float ws[8];
    int lane = threadIdx.x & 31, w = threadIdx.x >> 5;
    if (lane == 0) ws[w] = s;
    __syncthreads();
    if (w == 0) {
        s = lane < (blockDim.x >> 5) ? ws[lane] : 0.f;
#pragma unroll
        for (int o = 4; o; o >>= 1) s += __shfl_xor_sync(0xffu, s, o);
        if (lane == 0) atomicAdd(&g_acc, (double)s);
    }
}

__global__ void finalize_loss(float* out)
{
    const double LOG2PI = 1.8378770664093453;
    out[0] = (float)(g_acc / (double)((size_t)T_ * B_) +
                     0.5 * LOG2PI * (double)(OBS_ + ACT_ + ACT_));
}

// ---------------- launch ----------------
extern "C" void kernel_launch(void* const* d_in, const int* in_sizes, int n_in,
                              void* d_out, int out_size)
{
    const float* obs    = (const float*)d_in[0];
    const float* action = (const float*)d_in[1];
    const float* w_ih = (const float*)d_in[3];
    const float* w_hh = (const float*)d_in[4];
    const float* b_ih = (const float*)d_in[5];
    const float* b_hh = (const float*)d_in[6];
    const float *ow0 = (const float*)d_in[7],  *ob0 = (const float*)d_in[8];
    const float *ow1 = (const float*)d_in[9],  *ob1 = (const float*)d_in[10];
    const float *ow2 = (const float*)d_in[11], *ob2 = (const float*)d_in[12];
    const float *aw0 = (const float*)d_in[13], *ab0 = (const float*)d_in[14];
    const float *aw1 = (const float*)d_in[15], *ab1 = (const float*)d_in[16];
    const float *aw2 = (const float*)d_in[17], *ab2 = (const float*)d_in[18];
    const float *rw0 = (const float*)d_in[19], *rb0 = (const float*)d_in[20];
    const float *rw1 = (const float*)d_in[21], *rb1 = (const float*)d_in[22];
    const float *rw2 = (const float*)d_in[23], *rb2 = (const float*)d_in[24];

    float* out = (float*)d_out;
    float* pre_obs = out + 1;
    float* pre_act = pre_obs + (size_t)T_ * B_ * OBS_;
    float* pre_rew = pre_act + (size_t)T_ * B_ * ACT_;

    float *pX, *pgi, *pgi0, *phs, *pt1, *pt2, *pwhi, *pwlo, *pwcat, *pbcat;
    cudaGetSymbolAddress((void**)&pX,   g_X);
    cudaGetSymbolAddress((void**)&pgi,  g_gi);
    cudaGetSymbolAddress((void**)&pgi0, g_gi0);
    cudaGetSymbolAddress((void**)&phs,  g_hs);
    cudaGetSymbolAddress((void**)&pt1,  g_t1);
    cudaGetSymbolAddress((void**)&pt2,  g_t2);
    cudaGetSymbolAddress((void**)&pwhi, g_whi);
    cudaGetSymbolAddress((void**)&pwlo, g_wlo);
    cudaGetSymbolAddress((void**)&pwcat, g_wcat);
    cudaGetSymbolAddress((void**)&pbcat, g_bcat);

    static int smem_set = 0;
    if (!smem_set) {
        cudaFuncSetAttribute(gru_persist, cudaFuncAttributeMaxDynamicSharedMemorySize, GRU_SMEM);
        smem_set = 1;
    }

    const int M = T_ * B_;  // 131072

    loss_init<<<1, 1>>>();

    {
        size_t n = (size_t)T_ * B_ * IN_;
        pack_x<<<(unsigned)((n + 255) / 256), 256>>>(obs, action);
    }

    split_w<<<(G3_ * HID_ + 255) / 256, 256>>>(w_hh, pwhi, pwlo, G3_ * HID_);
    concat_w<<<(HF_ * HID_ + 255) / 256, 256>>>(ow0, aw0, rw0, ob0, ab0, rb0);

    gemm_tc<0, 1><<<dim3(G3_ / 128, M / 128), 256>>>(
        pX, IN_, w_ih, IN_, b_ih, pgi, G3_, M, G3_, IN_);

    gemm_tc<0, 1><<<dim3(G3_ / 128, B_ / 128), 256>>>(
        obs, OBS_, w_ih, IN_, b_ih, pgi0, G3_, B_, G3_, OBS_);

    h0_kernel<<<(B_ * HID_ + 255) / 256, 256>>>(b_hh);

    gru_persist<<<dim3(HID_ / 16, B_ / 64), 256, GRU_SMEM>>>(pwhi, pwlo, b_hh);

    // ---- fused MLP layer 1 (obs|act|rew): [M,512] -> [M,1536] ----
    gemm_tc<1, 1><<<dim3(G3_ / 128, M / 128), 256>>>(
        phs, HID_, pwcat, HID_, pbcat, pt1, G3_, M, G3_, HID_);

    // ---- obs path ----
    gemm_tc<1, 1><<<dim3(HF_ / 128, M / 128), 256>>>(pt1, G3_, ow1, HF_, ob1, pt2, HF_, M, HF_, HF_);
    gemm_tc<0, 0><<<dim3(1, M / 128), 256>>>(pt2, HF_, ow2, HF_, ob2, pre_obs, OBS_, M, OBS_, HF_);
    sq_loss<<<4096, 256>>>(obs, pre_obs, (size_t)M * OBS_, 0);

    // ---- action path ----
    gemm_tc<1, 1><<<dim3(HF_ / 128, M / 128), 256>>>(pt1 + 512, G3_, aw1, HF_, ab1, pt2, HF_, M, HF_, HF_);
    gemm_tc<0, 0><<<dim3(1, M / 128), 256>>>(pt2, HF_, aw2, HF_, ab2, pre_act, ACT_, M, ACT_, HF_);
    sq_loss<<<4096, 256>>>(action, pre_act, (size_t)M * ACT_, 0);

    // ---- reward path ----
    gemm_tc<1, 1><<<dim3(HF_ / 128, M / 128), 256>>>(pt1 + 1024, G3_, rw1, HF_, rb1, pt2, HF_, M, HF_, HF_);
    gemv_rw<<<(M * 32 + 255) / 256, 256>>>(pt2, rw2, rb2, pre_rew, M);
    sq_loss<<<4096, 256>>>(action, pre_rew, (size_t)M * ACT_, 5);

    finalize_loss<<<1, 1>>>(out);
}